// round 4
// baseline (speedup 1.0000x reference)
#include <cuda_runtime.h>
#include <math.h>
#include <stdint.h>

#define DIM      128
#define HEADS    8
#define DH       16
#define FFD      512
#define DEPTH    4
#define EPSV     1e-5f
#define NTHREADS 512
#define NWARPS   16
#define KCHUNK   16
#define NPAD     66          // padded token stride for transposed tiles

// Intermediate between channel stack and temporal stack: [64 batch][64 patch][128]
__device__ float g_mid[64 * 64 * DIM];

struct StackParams {
    const float *Wq, *Wk, *Wv, *Wo, *bo;
    const float *g1, *be1, *g2, *be2;
    const float *W1, *bf1, *W2, *bf2;
};

__device__ __forceinline__ float gelu_tanh(float x) {
    float x3 = x * x * x;
    return 0.5f * x * (1.0f + tanhf(0.7978845608028654f * (x + 0.044715f * x3)));
}

// ---------------- packed f32x2 helpers ----------------
__device__ __forceinline__ unsigned long long packdup(float x) {
    unsigned long long r; unsigned u = __float_as_uint(x);
    asm("mov.b64 %0, {%1,%1};" : "=l"(r) : "r"(u));
    return r;
}
__device__ __forceinline__ unsigned long long fma2(unsigned long long a,
                                                   unsigned long long b,
                                                   unsigned long long c) {
    unsigned long long d;
    asm("fma.rn.f32x2 %0, %1, %2, %3;" : "=l"(d) : "l"(a), "l"(b), "l"(c));
    return d;
}
__device__ __forceinline__ float2 unpack2(unsigned long long v) {
    unsigned lo, hi;
    asm("mov.b64 {%0,%1}, %2;" : "=r"(lo), "=r"(hi) : "l"(v));
    return make_float2(__uint_as_float(lo), __uint_as_float(hi));
}

// ---------------- cp.async helpers ----------------
__device__ __forceinline__ void cp16(void* dst, const void* src) {
    uint32_t d = (uint32_t)__cvta_generic_to_shared(dst);
    asm volatile("cp.async.ca.shared.global [%0], [%1], 16;" :: "r"(d), "l"(src));
}
__device__ __forceinline__ void cp_commit() { asm volatile("cp.async.commit_group;"); }
__device__ __forceinline__ void cp_wait0()  { asm volatile("cp.async.wait_group 0;"); }

// Stage one KCHUNK x 128 chunk of W (row stride ldw) into smem. 512 threads.
__device__ __forceinline__ void stage_chunk(float* __restrict__ dst,
                                            const float* __restrict__ src,
                                            int ldw, int tid)
{
    int r  = tid >> 5;
    int c4 = tid & 31;
    cp16(dst + r * DIM + c4 * 4, src + (size_t)r * ldw + c4 * 4);
}

// ---------------------------------------------------------------------------
// Token-packed f32x2 GEMM.
// C[N tokens x 128 cols] = At^T @ W  where At is [K][NPAD] (transposed acts,
// smem) and W is [K x 128-slice] (gmem, stride ldw), staged via cp.async.
// Thread map: token octet = wy>>1 (8 tokens), colpair = (wy&1)*32 + tx (2 cols).
// acc2[j][p] = f32x2 over token pair p (tokens t0+2p, t0+2p+1), col c0+j.
// CMODE: 0 = row-major store, 1 = row-major accumulate (+=), 2 = transposed
// store into Ct[col][token] (stride ldc).
// Ends with __syncthreads().
// ---------------------------------------------------------------------------
template<int N, int K, int CMODE, bool GELU_, bool BIAS>
__device__ __forceinline__ void gemm2(
    const float* __restrict__ At,
    const float* __restrict__ W, int ldw,
    const float* __restrict__ bias,
    float* __restrict__ C, int ldc,
    float* __restrict__ wbuf, int tid)
{
    const int tx = tid & 31;
    const int wy = tid >> 5;
    const int t0 = (wy >> 1) * 8;
    const int c0 = ((wy & 1) * 32 + tx) * 2;

    unsigned long long acc2[2][4];
#pragma unroll
    for (int j = 0; j < 2; j++)
#pragma unroll
        for (int p = 0; p < 4; p++) acc2[j][p] = 0ull;

    constexpr int NCH = K / KCHUNK;

    stage_chunk(wbuf, W, ldw, tid);
    cp_commit();

    for (int ch = 0; ch < NCH; ch++) {
        cp_wait0();
        __syncthreads();
        if (ch + 1 < NCH) {
            stage_chunk(wbuf + ((ch + 1) & 1) * (KCHUNK * DIM),
                        W + (size_t)(ch + 1) * KCHUNK * ldw, ldw, tid);
            cp_commit();
        }
        const float* wb = wbuf + (ch & 1) * (KCHUNK * DIM);
        const float* Ab = At + (size_t)ch * KCHUNK * NPAD + t0;
#pragma unroll
        for (int kk = 0; kk < KCHUNK; kk++) {
            const unsigned long long* ap =
                reinterpret_cast<const unsigned long long*>(Ab + kk * NPAD);
            unsigned long long a0 = ap[0];
            unsigned long long a1 = ap[1];
            unsigned long long a2 = ap[2];
            unsigned long long a3 = ap[3];
            float2 wv = *(const float2*)(wb + kk * DIM + c0);
            unsigned long long w0 = packdup(wv.x);
            unsigned long long w1 = packdup(wv.y);
            acc2[0][0] = fma2(a0, w0, acc2[0][0]);
            acc2[0][1] = fma2(a1, w0, acc2[0][1]);
            acc2[0][2] = fma2(a2, w0, acc2[0][2]);
            acc2[0][3] = fma2(a3, w0, acc2[0][3]);
            acc2[1][0] = fma2(a0, w1, acc2[1][0]);
            acc2[1][1] = fma2(a1, w1, acc2[1][1]);
            acc2[1][2] = fma2(a2, w1, acc2[1][2]);
            acc2[1][3] = fma2(a3, w1, acc2[1][3]);
        }
    }

#pragma unroll
    for (int j = 0; j < 2; j++) {
        float b = 0.f;
        if (BIAS) b = bias[c0 + j];
        if (CMODE == 2) {
            float* dst = C + (size_t)(c0 + j) * ldc;
#pragma unroll
            for (int p = 0; p < 4; p++) {
                int t = t0 + 2 * p;
                if (t + 1 < N) {
                    float2 v = unpack2(acc2[j][p]);
                    if (BIAS) { v.x += b; v.y += b; }
                    if (GELU_) { v.x = gelu_tanh(v.x); v.y = gelu_tanh(v.y); }
                    *(float2*)(dst + t) = v;
                }
            }
        } else {
#pragma unroll
            for (int p = 0; p < 4; p++) {
                int t = t0 + 2 * p;
                if (t + 1 < N) {
                    float2 v = unpack2(acc2[j][p]);
                    if (BIAS) { v.x += b; v.y += b; }
                    if (GELU_) { v.x = gelu_tanh(v.x); v.y = gelu_tanh(v.y); }
                    float* d0 = C + (size_t)t * ldc + c0 + j;
                    float* d1 = d0 + ldc;
                    if (CMODE == 1) { *d0 += v.x; *d1 += v.y; }
                    else            { *d0 = v.x;  *d1 = v.y; }
                }
            }
        }
    }
    __syncthreads();
}

// ---------------------------------------------------------------------------
// LayerNorm: reads h row-major [N][128], writes TRANSPOSED dstT [128][NPAD].
template<int N>
__device__ __forceinline__ void layernorm_T(
    const float* __restrict__ src, float* __restrict__ dstT,
    const float* __restrict__ g, const float* __restrict__ b, int tid)
{
    int lane = tid & 31, wid = tid >> 5;
    float4 g4 = *(const float4*)(g + lane * 4);
    float4 b4 = *(const float4*)(b + lane * 4);
    for (int c = wid; c < N; c += NWARPS) {
        float4 x = *(const float4*)(src + c * DIM + lane * 4);
        float s = x.x + x.y + x.z + x.w;
#pragma unroll
        for (int o = 16; o; o >>= 1) s += __shfl_xor_sync(0xffffffffu, s, o);
        float m = s * (1.0f / DIM);
        float dx = x.x - m, dy = x.y - m, dz = x.z - m, dw = x.w - m;
        float v = dx * dx + dy * dy + dz * dz + dw * dw;
#pragma unroll
        for (int o = 16; o; o >>= 1) v += __shfl_xor_sync(0xffffffffu, v, o);
        float rs = rsqrtf(v * (1.0f / DIM) + EPSV);
        int col = lane * 4;
        dstT[(col + 0) * NPAD + c] = dx * rs * g4.x + b4.x;
        dstT[(col + 1) * NPAD + c] = dy * rs * g4.y + b4.y;
        dstT[(col + 2) * NPAD + c] = dz * rs * g4.z + b4.z;
        dstT[(col + 3) * NPAD + c] = dw * rs * g4.w + b4.w;
    }
}

// softmax over the 16-feature head dim on row-major q, then * dh^-0.5
template<int N>
__device__ __forceinline__ void softmax_feat(float* __restrict__ q, int tid)
{
    int lane = tid & 31, wid = tid >> 5;
    for (int c = wid; c < N; c += NWARPS) {
        float4 x = *(const float4*)(q + c * DIM + lane * 4);
        float m = fmaxf(fmaxf(x.x, x.y), fmaxf(x.z, x.w));
        m = fmaxf(m, __shfl_xor_sync(0xffffffffu, m, 1));
        m = fmaxf(m, __shfl_xor_sync(0xffffffffu, m, 2));
        float4 e;
        e.x = expf(x.x - m); e.y = expf(x.y - m);
        e.z = expf(x.z - m); e.w = expf(x.w - m);
        float s = e.x + e.y + e.z + e.w;
        s += __shfl_xor_sync(0xffffffffu, s, 1);
        s += __shfl_xor_sync(0xffffffffu, s, 2);
        float sc = 0.25f / s;
        e.x *= sc; e.y *= sc; e.z *= sc; e.w *= sc;
        *(float4*)(q + c * DIM + lane * 4) = e;
    }
}

// softmax over the sequence dim on TRANSPOSED kT [128][NPAD] (contiguous rows)
template<int N>
__device__ __forceinline__ void softmax_seq_T(float* __restrict__ kT, int tid)
{
    if (tid < DIM) {
        float* p = kT + tid * NPAD;
        float m = -1e30f;
        for (int c = 0; c < N; c++) m = fmaxf(m, p[c]);
        float s = 0.f;
        for (int c = 0; c < N; c++) {
            float e = expf(p[c] - m);
            p[c] = e;
            s += e;
        }
        float inv = 1.0f / s;
        for (int c = 0; c < N; c++) p[c] *= inv;
    }
}

// ctx[h][d][e] = sum_c kT[h*16+d][c] * vT[h*16+e][c]  (contiguous rows)
template<int N>
__device__ __forceinline__ void compute_ctx_T(
    const float* __restrict__ kT, const float* __restrict__ vT,
    float* __restrict__ ctx, int tid)
{
    for (int o = tid; o < HEADS * DH * DH; o += NTHREADS) {
        int hh = o >> 8, d = (o >> 4) & 15, e = o & 15;
        const float* kp = kT + (hh * DH + d) * NPAD;
        const float* vp = vT + (hh * DH + e) * NPAD;
        float a = 0.f;
#pragma unroll 4
        for (int c = 0; c < N; c += 2) {       // N even; rows 8B-aligned
            float2 k2 = *(const float2*)(kp + c);
            float2 v2 = *(const float2*)(vp + c);
            a += k2.x * v2.x + k2.y * v2.y;
        }
        ctx[o] = a;
    }
}

// oT[col][c] = sum_d q[c][h*16+d] * ctx[h][d][col&15]   (writes transposed)
template<int N>
__device__ __forceinline__ void apply_ctx_T(
    const float* __restrict__ q, const float* __restrict__ ctx,
    float* __restrict__ oT, int tid)
{
    int tx = tid & 31, ty = tid >> 5;
    int hh = tx >> 2;
    int ecol = (tx & 3) * 4;
    for (int c = ty; c < N; c += NWARPS) {
        float4 acc = make_float4(0.f, 0.f, 0.f, 0.f);
        const float* qp = q + c * DIM + hh * DH;
        const float* cp = ctx + hh * DH * DH + ecol;
#pragma unroll
        for (int d = 0; d < DH; d++) {
            float qv = qp[d];
            float4 cv = *(const float4*)(cp + d * DH);
            acc.x += qv * cv.x; acc.y += qv * cv.y;
            acc.z += qv * cv.z; acc.w += qv * cv.w;
        }
        int col = hh * DH + ecol;
        oT[(col + 0) * NPAD + c] = acc.x;
        oT[(col + 1) * NPAD + c] = acc.y;
        oT[(col + 2) * NPAD + c] = acc.z;
        oT[(col + 3) * NPAD + c] = acc.w;
    }
}

template<int N>
__device__ __forceinline__ void mean_rows(
    const float* __restrict__ h, float* __restrict__ out, int tid)
{
    if (tid < DIM) {
        float s = 0.f;
        for (int c = 0; c < N; c++) s += h[c * DIM + tid];
        out[tid] = s * (1.0f / N);
    }
}

// ---------------------------------------------------------------------------
// One CTA = one sequence. Full 4-layer stack in SMEM.
// SMEM: h[N*128] | xnT[128*NPAD] | big | wbuf[2*16*128]
//   attn: big = Q[N*128] | kT[128*NPAD] | vT[128*NPAD] | ctx[2048]
//         (oT reuses xnT after QKV)
//   ff:   big = tT[512*NPAD]  (xn2T reuses xnT slot)
// ---------------------------------------------------------------------------
template<int N, int MODE>
__global__ void __launch_bounds__(NTHREADS, 1)
stack_kernel(const float* __restrict__ xin, float* __restrict__ gout, StackParams P)
{
    extern __shared__ float sm[];
    float* h    = sm;
    float* xnT  = sm + N * DIM;                 // also oT / xn2T
    float* big  = xnT + DIM * NPAD;
    float* wbuf = big + FFD * NPAD;

    float* Q   = big;
    float* kT  = Q + N * DIM;
    float* vT  = kT + DIM * NPAD;
    float* ctx = vT + DIM * NPAD;
    float* tT  = big;

    const int tid = threadIdx.x;

    // -------- load sequence into h --------
    if (MODE == 0) {
        int s = blockIdx.x;
        int b = s >> 6, p = s & 63;
        const float* xb = xin + (size_t)b * DIM * 62 * 64 + p;
        for (int i = tid; i < N * DIM; i += NTHREADS) {
            int c = i >> 7, e = i & 127;
            h[i] = xb[(e * 62 + c) * 64];
        }
    } else {
        const float* xb = g_mid + (size_t)blockIdx.x * N * DIM;
        for (int i = tid; i < N * DIM; i += NTHREADS) h[i] = xb[i];
    }
    __syncthreads();

    for (int l = 0; l < DEPTH; l++) {
        const float* Wq  = P.Wq  + l * DIM * DIM;
        const float* Wk  = P.Wk  + l * DIM * DIM;
        const float* Wv  = P.Wv  + l * DIM * DIM;
        const float* Wo  = P.Wo  + l * DIM * DIM;
        const float* bo  = P.bo  + l * DIM;
        const float* g1  = P.g1  + l * DIM;
        const float* be1 = P.be1 + l * DIM;
        const float* g2  = P.g2  + l * DIM;
        const float* be2 = P.be2 + l * DIM;
        const float* W1  = P.W1  + l * DIM * FFD;
        const float* bf1 = P.bf1 + l * FFD;
        const float* W2  = P.W2  + l * FFD * DIM;
        const float* bf2 = P.bf2 + l * DIM;

        // ---- attention ----
        layernorm_T<N>(h, xnT, g1, be1, tid);
        __syncthreads();

        gemm2<N, DIM, 0, false, false>(xnT, Wq, DIM, nullptr, Q, DIM, wbuf, tid);
        gemm2<N, DIM, 2, false, false>(xnT, Wk, DIM, nullptr, kT, NPAD, wbuf, tid);
        gemm2<N, DIM, 2, false, false>(xnT, Wv, DIM, nullptr, vT, NPAD, wbuf, tid);

        softmax_feat<N>(Q, tid);
        softmax_seq_T<N>(kT, tid);
        __syncthreads();

        compute_ctx_T<N>(kT, vT, ctx, tid);
        __syncthreads();

        apply_ctx_T<N>(Q, ctx, xnT, tid);   // oT -> xnT slot
        __syncthreads();

        gemm2<N, DIM, 1, false, true>(xnT, Wo, DIM, bo, h, DIM, wbuf, tid);

        // ---- feed-forward ----
        layernorm_T<N>(h, xnT, g2, be2, tid);   // xn2T -> xnT slot
        __syncthreads();

#pragma unroll
        for (int j = 0; j < 4; j++) {
            gemm2<N, DIM, 2, true, true>(xnT,
                                         W1 + j * DIM, FFD,
                                         bf1 + j * DIM,
                                         tT + (size_t)j * DIM * NPAD, NPAD,
                                         wbuf, tid);
        }

        gemm2<N, FFD, 1, false, true>(tT, W2, DIM, bf2, h, DIM, wbuf, tid);
    }

    // -------- mean over tokens --------
    if (MODE == 0) {
        mean_rows<N>(h, g_mid + (size_t)blockIdx.x * DIM, tid);
    } else {
        mean_rows<N>(h, gout + (size_t)blockIdx.x * DIM, tid);
    }
}

// ---------------------------------------------------------------------------
static StackParams mk_params(void* const* d_in, int base)
{
    StackParams p;
    p.Wq  = (const float*)d_in[base + 0];
    p.Wk  = (const float*)d_in[base + 1];
    p.Wv  = (const float*)d_in[base + 2];
    p.Wo  = (const float*)d_in[base + 3];
    p.bo  = (const float*)d_in[base + 4];
    p.g1  = (const float*)d_in[base + 5];
    p.be1 = (const float*)d_in[base + 6];
    p.g2  = (const float*)d_in[base + 7];
    p.be2 = (const float*)d_in[base + 8];
    p.W1  = (const float*)d_in[base + 9];
    p.bf1 = (const float*)d_in[base + 10];
    p.W2  = (const float*)d_in[base + 11];
    p.bf2 = (const float*)d_in[base + 12];
    return p;
}

extern "C" void kernel_launch(void* const* d_in, const int* in_sizes, int n_in,
                              void* d_out, int out_size)
{
    (void)in_sizes; (void)n_in; (void)out_size;

    const float* x = (const float*)d_in[0];
    StackParams Pc = mk_params(d_in, 1);
    StackParams Pt = mk_params(d_in, 14);

    const int SMEM_A = (62 * DIM + DIM * NPAD + FFD * NPAD + 2 * KCHUNK * DIM)
                       * (int)sizeof(float);   // 217,088 B
    const int SMEM_B = (64 * DIM + DIM * NPAD + FFD * NPAD + 2 * KCHUNK * DIM)
                       * (int)sizeof(float);   // 218,112 B

    cudaFuncSetAttribute(stack_kernel<62, 0>,
                         cudaFuncAttributeMaxDynamicSharedMemorySize, SMEM_A);
    cudaFuncSetAttribute(stack_kernel<64, 1>,
                         cudaFuncAttributeMaxDynamicSharedMemorySize, SMEM_B);

    // channel stack: 64 batches * 64 patches sequences of length 62
    stack_kernel<62, 0><<<4096, NTHREADS, SMEM_A>>>(x, nullptr, Pc);
    // temporal stack: 64 sequences of length 64 (reads g_mid, writes d_out)
    stack_kernel<64, 1><<<64, NTHREADS, SMEM_B>>>(nullptr, (float*)d_out, Pt);
}